// round 1
// baseline (speedup 1.0000x reference)
#include <cuda_runtime.h>

// ---------------------------------------------------------------------------
// MultiHeadAttention: B=2, S=2048, D=1024, H=16, Dh=64, fp32.
// Round 1: correct SIMT fp32 baseline.
//   K1: fused QKV GEMM (128x128x8 tiles) + RoPE epilogue -> (B,H,S,Dh) scratch
//   K2: flash attention, 64 q-rows per block, online softmax
//   K3: output projection GEMM -> d_out
// ---------------------------------------------------------------------------

constexpr int BB = 2;
constexpr int SS = 2048;
constexpr int DD = 1024;
constexpr int HH = 16;
constexpr int DH = 64;
constexpr int MT = BB * SS;   // 4096 rows

// Scratch (allocation-free: device globals)
__device__ float g_q[BB * HH * SS * DH];
__device__ float g_k[BB * HH * SS * DH];
__device__ float g_v[BB * HH * SS * DH];
__device__ float g_att[MT * DD];

// ---------------------------------------------------------------------------
// Fused QKV GEMM + RoPE.
// C = x(4096x1024) @ w(1024x1024); blockIdx.z selects q/k/v.
// 128x128 tile, BK=8, 256 threads, 8x8 per thread (2x2 quads of 4x4).
// Epilogue: RoPE for q,k; store to (B,H,S,Dh).
// ---------------------------------------------------------------------------
__global__ __launch_bounds__(256) void qkv_kernel(
    const float* __restrict__ x,
    const float* __restrict__ wq, const float* __restrict__ wk,
    const float* __restrict__ wv,
    const float* __restrict__ cosT, const float* __restrict__ sinT)
{
    const int mat = blockIdx.z;
    const float* __restrict__ w = (mat == 0) ? wq : (mat == 1) ? wk : wv;
    float* __restrict__ out = (mat == 0) ? g_q : (mat == 1) ? g_k : g_v;

    __shared__ float As[8][128];
    __shared__ float Bs[8][128];

    const int tid = threadIdx.x;
    const int tx = tid & 15;
    const int ty = tid >> 4;
    const int brow = blockIdx.y * 128;
    const int bcol = blockIdx.x * 128;

    float acc[8][8];
#pragma unroll
    for (int i = 0; i < 8; i++)
#pragma unroll
        for (int j = 0; j < 8; j++) acc[i][j] = 0.f;

    const int aRow = tid >> 1;       // 0..127
    const int aK   = (tid & 1) * 4;  // 0 or 4
    const int bRow = tid >> 5;       // 0..7
    const int bCol = (tid & 31) * 4; // 0..124

    for (int k0 = 0; k0 < DD; k0 += 8) {
        float4 av = *reinterpret_cast<const float4*>(
            x + (size_t)(brow + aRow) * DD + k0 + aK);
        As[aK + 0][aRow] = av.x;
        As[aK + 1][aRow] = av.y;
        As[aK + 2][aRow] = av.z;
        As[aK + 3][aRow] = av.w;
        *reinterpret_cast<float4*>(&Bs[bRow][bCol]) =
            *reinterpret_cast<const float4*>(
                w + (size_t)(k0 + bRow) * DD + bcol + bCol);
        __syncthreads();
#pragma unroll
        for (int k = 0; k < 8; k++) {
            float ra[8], rb[8];
            *reinterpret_cast<float4*>(&ra[0]) =
                *reinterpret_cast<const float4*>(&As[k][ty * 4]);
            *reinterpret_cast<float4*>(&ra[4]) =
                *reinterpret_cast<const float4*>(&As[k][64 + ty * 4]);
            *reinterpret_cast<float4*>(&rb[0]) =
                *reinterpret_cast<const float4*>(&Bs[k][tx * 4]);
            *reinterpret_cast<float4*>(&rb[4]) =
                *reinterpret_cast<const float4*>(&Bs[k][64 + tx * 4]);
#pragma unroll
            for (int i = 0; i < 8; i++)
#pragma unroll
                for (int j = 0; j < 8; j++) acc[i][j] = fmaf(ra[i], rb[j], acc[i][j]);
        }
        __syncthreads();
    }

    // Epilogue: RoPE (q,k) + scatter to (B,H,S,Dh)
#pragma unroll
    for (int ri = 0; ri < 2; ri++) {
#pragma unroll
        for (int i = 0; i < 4; i++) {
            const int rr = brow + ri * 64 + ty * 4 + i;
            const int bb = rr >> 11;       // / 2048
            const int ss = rr & (SS - 1);  // % 2048
#pragma unroll
            for (int cj = 0; cj < 2; cj++) {
                const int c0 = bcol + cj * 64 + tx * 4;  // multiple of 4
                float v0 = acc[ri * 4 + i][cj * 4 + 0];
                float v1 = acc[ri * 4 + i][cj * 4 + 1];
                float v2 = acc[ri * 4 + i][cj * 4 + 2];
                float v3 = acc[ri * 4 + i][cj * 4 + 3];
                const int dh = c0 & (DH - 1);
                if (mat < 2) {
                    const int fi = ss * 32 + (dh >> 1);
                    const float c_0 = cosT[fi],     s_0 = sinT[fi];
                    const float c_1 = cosT[fi + 1], s_1 = sinT[fi + 1];
                    const float o0 = v0 * c_0 - v1 * s_0;
                    const float o1 = v0 * s_0 + v1 * c_0;
                    const float o2 = v2 * c_1 - v3 * s_1;
                    const float o3 = v2 * s_1 + v3 * c_1;
                    v0 = o0; v1 = o1; v2 = o2; v3 = o3;
                }
                const int hh = c0 >> 6;
                float* dst = out + (((size_t)(bb * HH + hh) * SS + ss) * DH + dh);
                float4 st = make_float4(v0, v1, v2, v3);
                *reinterpret_cast<float4*>(dst) = st;
            }
        }
    }
}

// ---------------------------------------------------------------------------
// Flash attention. grid = (S/64, H, B), block = 256 (16x16, 4x4 per thread).
// smem: Qt[d][qr] 64x65, Kt[d][kr] 64x65, Pt[kr][qr] 64x65, Vs[kr][d] 64x64.
// ---------------------------------------------------------------------------
__global__ __launch_bounds__(256) void attn_kernel(float* __restrict__ gout)
{
    extern __shared__ float sm[];
    float (*Qt)[65] = reinterpret_cast<float(*)[65]>(sm);
    float (*Kt)[65] = reinterpret_cast<float(*)[65]>(sm + 64 * 65);
    float (*Pt)[65] = reinterpret_cast<float(*)[65]>(sm + 2 * 64 * 65);
    float (*Vs)[64] = reinterpret_cast<float(*)[64]>(sm + 3 * 64 * 65);

    const int qt = blockIdx.x;
    const int h  = blockIdx.y;
    const int b  = blockIdx.z;
    const float* __restrict__ Q = g_q + (((size_t)(b * HH + h) * SS) + qt * 64) * DH;
    const float* __restrict__ K = g_k + ((size_t)(b * HH + h) * SS) * DH;
    const float* __restrict__ V = g_v + ((size_t)(b * HH + h) * SS) * DH;

    const int tid = threadIdx.x;
    const int tx = tid & 15;
    const int ty = tid >> 4;

    // Q tile, transposed, with 1/sqrt(Dh)=0.125 folded in
    for (int i = tid; i < 64 * 64; i += 256) {
        const int r = i >> 6, d = i & 63;
        Qt[d][r] = Q[i] * 0.125f;
    }

    float m_i[4], l_i[4], o[4][4];
#pragma unroll
    for (int i = 0; i < 4; i++) {
        m_i[i] = -1e30f;
        l_i[i] = 0.f;
#pragma unroll
        for (int j = 0; j < 4; j++) o[i][j] = 0.f;
    }

    for (int kt = 0; kt < SS / 64; ++kt) {
        __syncthreads();  // protect Kt/Vs/Pt from previous iteration's readers
        const float* __restrict__ Kp = K + kt * 64 * DH;
        const float* __restrict__ Vp = V + kt * 64 * DH;
        for (int i = tid; i < 64 * 64; i += 256) {
            const int r = i >> 6, d = i & 63;
            Kt[d][r] = Kp[i];
            Vs[r][d] = Vp[i];
        }
        __syncthreads();

        // S = Q @ K^T   (per thread: 4 q-rows x 4 k-cols)
        float sc[4][4];
#pragma unroll
        for (int i = 0; i < 4; i++)
#pragma unroll
            for (int j = 0; j < 4; j++) sc[i][j] = 0.f;

#pragma unroll 8
        for (int d = 0; d < 64; ++d) {
            float qa[4], kb[4];
#pragma unroll
            for (int i = 0; i < 4; i++) qa[i] = Qt[d][ty * 4 + i];
#pragma unroll
            for (int j = 0; j < 4; j++) kb[j] = Kt[d][tx * 4 + j];
#pragma unroll
            for (int i = 0; i < 4; i++)
#pragma unroll
                for (int j = 0; j < 4; j++) sc[i][j] = fmaf(qa[i], kb[j], sc[i][j]);
        }

        // Online softmax update (row stats shared across the 16 tx threads)
#pragma unroll
        for (int i = 0; i < 4; i++) {
            float mx = fmaxf(fmaxf(sc[i][0], sc[i][1]), fmaxf(sc[i][2], sc[i][3]));
            mx = fmaxf(mx, __shfl_xor_sync(0xffffffffu, mx, 1));
            mx = fmaxf(mx, __shfl_xor_sync(0xffffffffu, mx, 2));
            mx = fmaxf(mx, __shfl_xor_sync(0xffffffffu, mx, 4));
            mx = fmaxf(mx, __shfl_xor_sync(0xffffffffu, mx, 8));
            const float mnew = fmaxf(m_i[i], mx);
            const float corr = __expf(m_i[i] - mnew);
            m_i[i] = mnew;
            float rs = 0.f;
#pragma unroll
            for (int j = 0; j < 4; j++) {
                const float p = __expf(sc[i][j] - mnew);
                sc[i][j] = p;
                rs += p;
            }
            rs += __shfl_xor_sync(0xffffffffu, rs, 1);
            rs += __shfl_xor_sync(0xffffffffu, rs, 2);
            rs += __shfl_xor_sync(0xffffffffu, rs, 4);
            rs += __shfl_xor_sync(0xffffffffu, rs, 8);
            l_i[i] = l_i[i] * corr + rs;
#pragma unroll
            for (int j = 0; j < 4; j++) o[i][j] *= corr;
#pragma unroll
            for (int j = 0; j < 4; j++) Pt[tx * 4 + j][ty * 4 + i] = sc[i][j];
        }
        __syncthreads();

        // O += P @ V   (per thread: 4 q-rows x 4 dh-cols)
#pragma unroll 8
        for (int kk = 0; kk < 64; ++kk) {
            float pa[4], vb[4];
#pragma unroll
            for (int i = 0; i < 4; i++) pa[i] = Pt[kk][ty * 4 + i];
#pragma unroll
            for (int j = 0; j < 4; j++) vb[j] = Vs[kk][tx * 4 + j];
#pragma unroll
            for (int i = 0; i < 4; i++)
#pragma unroll
                for (int j = 0; j < 4; j++) o[i][j] = fmaf(pa[i], vb[j], o[i][j]);
        }
    }

    // Write (b, s, h*64+dh) into g_att
#pragma unroll
    for (int i = 0; i < 4; i++) {
        const float inv = 1.f / l_i[i];
        float4 st = make_float4(o[i][0] * inv, o[i][1] * inv,
                                o[i][2] * inv, o[i][3] * inv);
        float* dst = gout + ((size_t)(b * SS + qt * 64 + ty * 4 + i)) * DD
                     + h * DH + tx * 4;
        *reinterpret_cast<float4*>(dst) = st;
    }
}

// ---------------------------------------------------------------------------
// Output projection: d_out = g_att(4096x1024) @ wo(1024x1024)
// ---------------------------------------------------------------------------
__global__ __launch_bounds__(256) void proj_kernel(
    const float* __restrict__ wo, float* __restrict__ Cout)
{
    __shared__ float As[8][128];
    __shared__ float Bs[8][128];

    const int tid = threadIdx.x;
    const int tx = tid & 15;
    const int ty = tid >> 4;
    const int brow = blockIdx.y * 128;
    const int bcol = blockIdx.x * 128;

    float acc[8][8];
#pragma unroll
    for (int i = 0; i < 8; i++)
#pragma unroll
        for (int j = 0; j < 8; j++) acc[i][j] = 0.f;

    const int aRow = tid >> 1;
    const int aK   = (tid & 1) * 4;
    const int bRow = tid >> 5;
    const int bCol = (tid & 31) * 4;

    for (int k0 = 0; k0 < DD; k0 += 8) {
        float4 av = *reinterpret_cast<const float4*>(
            g_att + (size_t)(brow + aRow) * DD + k0 + aK);
        As[aK + 0][aRow] = av.x;
        As[aK + 1][aRow] = av.y;
        As[aK + 2][aRow] = av.z;
        As[aK + 3][aRow] = av.w;
        *reinterpret_cast<float4*>(&Bs[bRow][bCol]) =
            *reinterpret_cast<const float4*>(
                wo + (size_t)(k0 + bRow) * DD + bcol + bCol);
        __syncthreads();
#pragma unroll
        for (int k = 0; k < 8; k++) {
            float ra[8], rb[8];
            *reinterpret_cast<float4*>(&ra[0]) =
                *reinterpret_cast<const float4*>(&As[k][ty * 4]);
            *reinterpret_cast<float4*>(&ra[4]) =
                *reinterpret_cast<const float4*>(&As[k][64 + ty * 4]);
            *reinterpret_cast<float4*>(&rb[0]) =
                *reinterpret_cast<const float4*>(&Bs[k][tx * 4]);
            *reinterpret_cast<float4*>(&rb[4]) =
                *reinterpret_cast<const float4*>(&Bs[k][64 + tx * 4]);
#pragma unroll
            for (int i = 0; i < 8; i++)
#pragma unroll
                for (int j = 0; j < 8; j++) acc[i][j] = fmaf(ra[i], rb[j], acc[i][j]);
        }
        __syncthreads();
    }

#pragma unroll
    for (int ri = 0; ri < 2; ri++) {
#pragma unroll
        for (int i = 0; i < 4; i++) {
            const int rr = brow + ri * 64 + ty * 4 + i;
#pragma unroll
            for (int cj = 0; cj < 2; cj++) {
                const int cc = bcol + cj * 64 + tx * 4;
                float4 st = make_float4(acc[ri * 4 + i][cj * 4 + 0],
                                        acc[ri * 4 + i][cj * 4 + 1],
                                        acc[ri * 4 + i][cj * 4 + 2],
                                        acc[ri * 4 + i][cj * 4 + 3]);
                *reinterpret_cast<float4*>(Cout + (size_t)rr * DD + cc) = st;
            }
        }
    }
}

// ---------------------------------------------------------------------------
extern "C" void kernel_launch(void* const* d_in, const int* in_sizes, int n_in,
                              void* d_out, int out_size)
{
    const float* x    = (const float*)d_in[0];
    const float* cosT = (const float*)d_in[1];
    const float* sinT = (const float*)d_in[2];
    const float* wq   = (const float*)d_in[3];
    const float* wk   = (const float*)d_in[4];
    const float* wv   = (const float*)d_in[5];
    const float* wo   = (const float*)d_in[6];
    float* out = (float*)d_out;

    const int attn_smem = (3 * 64 * 65 + 64 * 64) * (int)sizeof(float);  // 66304
    cudaFuncSetAttribute(attn_kernel,
                         cudaFuncAttributeMaxDynamicSharedMemorySize, attn_smem);

    // 1) Q/K/V projections + RoPE
    qkv_kernel<<<dim3(DD / 128, MT / 128, 3), 256>>>(x, wq, wk, wv, cosT, sinT);

    // 2) Flash attention -> g_att  (via device-global scratch)
    {
        // g_att address is a device symbol; pass via kernel that takes a ptr?
        // attn_kernel writes through a pointer argument resolved on host side:
        // use the device symbol directly inside the kernel is not possible for
        // the argument form, so fetch once per launch (cheap, not captured as
        // a stream op). To stay graph-safe we instead pass the symbol through
        // a device-side reference: attn writes to g_att via pointer param.
        static float* att_ptr = nullptr;
        if (!att_ptr) cudaGetSymbolAddress((void**)&att_ptr, g_att);
        attn_kernel<<<dim3(SS / 64, HH, BB), 256, attn_smem>>>(att_ptr);
    }

    // 3) Output projection
    proj_kernel<<<dim3(DD / 128, MT / 128, 1), 256>>>(wo, out);
}

// round 2
// speedup vs baseline: 2.5946x; 2.5946x over previous
#include <cuda_runtime.h>
#include <cstdint>

// ---------------------------------------------------------------------------
// MultiHeadAttention B=2,S=2048,D=1024,H=16,Dh=64 fp32 — TF32 tensor-core round.
//   K1 qkv_mma : X@W{q,k,v} (4096x1024x1024) + RoPE -> (B,H,S,Dh) scratch
//   K2 attn_mma: flash attention, 128 q-rows/block, TF32 mma, online softmax
//   K3 proj_mma: att @ wo -> d_out
// ---------------------------------------------------------------------------

constexpr int BB = 2;
constexpr int SS = 2048;
constexpr int DD = 1024;
constexpr int HH = 16;
constexpr int DH = 64;
constexpr int MT = BB * SS;   // 4096

__device__ float g_q[BB * HH * SS * DH];
__device__ float g_k[BB * HH * SS * DH];
__device__ float g_v[BB * HH * SS * DH];
__device__ float g_att[MT * DD];

__device__ __forceinline__ uint32_t f2tf(float x) {
    uint32_t r;
    asm("cvt.rna.tf32.f32 %0, %1;" : "=r"(r) : "f"(x));
    return r;
}

__device__ __forceinline__ void mma8(float* d, uint32_t a0, uint32_t a1,
                                     uint32_t a2, uint32_t a3,
                                     uint32_t b0, uint32_t b1) {
    asm volatile(
        "mma.sync.aligned.m16n8k8.row.col.f32.tf32.tf32.f32 "
        "{%0,%1,%2,%3}, {%4,%5,%6,%7}, {%8,%9}, {%0,%1,%2,%3};"
        : "+f"(d[0]), "+f"(d[1]), "+f"(d[2]), "+f"(d[3])
        : "r"(a0), "r"(a1), "r"(a2), "r"(a3), "r"(b0), "r"(b1));
}

__device__ __forceinline__ float4 cvt4(float4 v) {
    float4 o;
    o.x = __uint_as_float(f2tf(v.x));
    o.y = __uint_as_float(f2tf(v.y));
    o.z = __uint_as_float(f2tf(v.z));
    o.w = __uint_as_float(f2tf(v.w));
    return o;
}

// ---------------------------------------------------------------------------
// K1: QKV GEMM + RoPE.  grid (8, 32, 3), block 256 (8 warps 2x4).
// smem: As[128][36] (stride 36 -> conflict-free frags), Bs[32][132].
// ---------------------------------------------------------------------------
__global__ __launch_bounds__(256) void qkv_mma(
    const float* __restrict__ x,
    const float* __restrict__ wq, const float* __restrict__ wk,
    const float* __restrict__ wv,
    const float* __restrict__ cosT, const float* __restrict__ sinT)
{
    __shared__ float As[128 * 36];
    __shared__ float Bs[32 * 132];

    const int mat = blockIdx.z;
    const float* __restrict__ w = (mat == 0) ? wq : (mat == 1) ? wk : wv;
    float* __restrict__ out = (mat == 0) ? g_q : (mat == 1) ? g_k : g_v;

    const int tid  = threadIdx.x;
    const int lane = tid & 31;
    const int warp = tid >> 5;
    const int wm = warp >> 2;   // 0..1
    const int wn = warp & 3;    // 0..3
    const int brow = blockIdx.y * 128;
    const int bcol = blockIdx.x * 128;

    float acc[4][4][4];
#pragma unroll
    for (int mi = 0; mi < 4; mi++)
#pragma unroll
        for (int ni = 0; ni < 4; ni++)
#pragma unroll
            for (int f = 0; f < 4; f++) acc[mi][ni][f] = 0.f;

    for (int kk = 0; kk < DD; kk += 32) {
        // stage A tile 128x32 (1024 float4)
#pragma unroll
        for (int i = 0; i < 4; i++) {
            int idx = tid + i * 256;
            int r = idx >> 3, c4 = (idx & 7) << 2;
            float4 v = *reinterpret_cast<const float4*>(
                x + (size_t)(brow + r) * DD + kk + c4);
            *reinterpret_cast<float4*>(&As[r * 36 + c4]) = cvt4(v);
        }
        // stage B tile 32x128
#pragma unroll
        for (int i = 0; i < 4; i++) {
            int idx = tid + i * 256;
            int r = idx >> 5, c4 = (idx & 31) << 2;
            float4 v = *reinterpret_cast<const float4*>(
                w + (size_t)(kk + r) * DD + bcol + c4);
            *reinterpret_cast<float4*>(&Bs[r * 132 + c4]) = cvt4(v);
        }
        __syncthreads();

#pragma unroll
        for (int ks = 0; ks < 4; ks++) {
            const int k0 = ks * 8;
            uint32_t a[4][4], b[4][2];
            const int ar  = wm * 64 + (lane >> 2);
            const int acl = k0 + (lane & 3);
#pragma unroll
            for (int mi = 0; mi < 4; mi++) {
                const float* p = &As[(ar + mi * 16) * 36 + acl];
                a[mi][0] = __float_as_uint(p[0]);
                a[mi][2] = __float_as_uint(p[4]);
                a[mi][1] = __float_as_uint(p[8 * 36]);
                a[mi][3] = __float_as_uint(p[8 * 36 + 4]);
            }
            const int bc = wn * 32 + (lane >> 2);
            const int br = k0 + (lane & 3);
#pragma unroll
            for (int ni = 0; ni < 4; ni++) {
                const float* p = &Bs[br * 132 + bc + ni * 8];
                b[ni][0] = __float_as_uint(p[0]);
                b[ni][1] = __float_as_uint(p[4 * 132]);
            }
#pragma unroll
            for (int mi = 0; mi < 4; mi++)
#pragma unroll
                for (int ni = 0; ni < 4; ni++)
                    mma8(acc[mi][ni], a[mi][0], a[mi][1], a[mi][2], a[mi][3],
                         b[ni][0], b[ni][1]);
        }
        __syncthreads();
    }

    // epilogue: RoPE + scatter (B,H,S,Dh)
    const int ar = wm * 64 + (lane >> 2);
    const int ac = wn * 32 + (lane & 3) * 2;
#pragma unroll
    for (int mi = 0; mi < 4; mi++) {
#pragma unroll
        for (int hp = 0; hp < 2; hp++) {
            const int row = brow + ar + mi * 16 + hp * 8;
            const int bb = row >> 11;
            const int ss = row & (SS - 1);
#pragma unroll
            for (int ni = 0; ni < 4; ni++) {
                const int col = bcol + ac + ni * 8;
                const int hh = col >> 6;
                const int dh = col & (DH - 1);
                float c0 = acc[mi][ni][hp * 2 + 0];
                float c1 = acc[mi][ni][hp * 2 + 1];
                if (mat < 2) {
                    const int fi = ss * 32 + (dh >> 1);
                    const float cs = cosT[fi], sn = sinT[fi];
                    const float o0 = c0 * cs - c1 * sn;
                    const float o1 = c0 * sn + c1 * cs;
                    c0 = o0; c1 = o1;
                }
                float2 st = make_float2(c0, c1);
                *reinterpret_cast<float2*>(
                    out + ((size_t)(bb * HH + hh) * SS + ss) * DH + dh) = st;
            }
        }
    }
}

// ---------------------------------------------------------------------------
// K2: flash attention.  grid (S/128, H, B), block 256 (8 warps, 16 rows each).
// smem (dynamic, stride 68): Qs[128], Ks[64], Vs[64], Ps[128]  -> 104448 B.
// ---------------------------------------------------------------------------
constexpr int ATT_SMEM = (128 + 64 + 64 + 128) * 68 * (int)sizeof(float);

__global__ __launch_bounds__(256) void attn_mma()
{
    extern __shared__ float sm[];
    float* Qs = sm;                  // [128][68]
    float* Ks = Qs + 128 * 68;       // [64][68]
    float* Vs = Ks + 64 * 68;        // [64][68]
    float* Ps = Vs + 64 * 68;        // [128][68]

    const int qt = blockIdx.x, h = blockIdx.y, b = blockIdx.z;
    const float* __restrict__ Q = g_q + ((size_t)(b * HH + h) * SS + qt * 128) * DH;
    const float* __restrict__ K = g_k + (size_t)(b * HH + h) * SS * DH;
    const float* __restrict__ V = g_v + (size_t)(b * HH + h) * SS * DH;

    const int tid = threadIdx.x;
    const int lane = tid & 31;
    const int warp = tid >> 5;

    // stage Q (scaled by 1/sqrt(Dh), tf32-rounded)
#pragma unroll
    for (int i = 0; i < 8; i++) {
        int idx = tid + i * 256;
        int r = idx >> 4, c4 = (idx & 15) << 2;
        float4 v = *reinterpret_cast<const float4*>(Q + r * DH + c4);
        v.x *= 0.125f; v.y *= 0.125f; v.z *= 0.125f; v.w *= 0.125f;
        *reinterpret_cast<float4*>(&Qs[r * 68 + c4]) = cvt4(v);
    }

    float mrow[2] = {-1e30f, -1e30f};
    float lrow[2] = {0.f, 0.f};
    float o[8][4];
#pragma unroll
    for (int ni = 0; ni < 8; ni++)
#pragma unroll
        for (int f = 0; f < 4; f++) o[ni][f] = 0.f;

    const int rbase = warp * 16 + (lane >> 2);

    for (int kt = 0; kt < SS / 64; kt++) {
        __syncthreads();   // protect Ks/Vs from previous iteration readers
        const float* __restrict__ Kp = K + (size_t)kt * 64 * DH;
        const float* __restrict__ Vp = V + (size_t)kt * 64 * DH;
#pragma unroll
        for (int i = 0; i < 4; i++) {
            int idx = tid + i * 256;
            int r = idx >> 4, c4 = (idx & 15) << 2;
            float4 kv = *reinterpret_cast<const float4*>(Kp + r * DH + c4);
            float4 vv = *reinterpret_cast<const float4*>(Vp + r * DH + c4);
            *reinterpret_cast<float4*>(&Ks[r * 68 + c4]) = cvt4(kv);
            *reinterpret_cast<float4*>(&Vs[r * 68 + c4]) = cvt4(vv);
        }
        __syncthreads();

        // S = Q @ K^T  (per warp: m16 x n64, k=64)
        float sacc[8][4];
#pragma unroll
        for (int ni = 0; ni < 8; ni++)
#pragma unroll
            for (int f = 0; f < 4; f++) sacc[ni][f] = 0.f;

#pragma unroll
        for (int ks = 0; ks < 8; ks++) {
            const int k0 = ks * 8;
            const float* ap = &Qs[rbase * 68 + k0 + (lane & 3)];
            const uint32_t a0 = __float_as_uint(ap[0]);
            const uint32_t a1 = __float_as_uint(ap[8 * 68]);
            const uint32_t a2 = __float_as_uint(ap[4]);
            const uint32_t a3 = __float_as_uint(ap[8 * 68 + 4]);
#pragma unroll
            for (int ni = 0; ni < 8; ni++) {
                const float* bp = &Ks[(ni * 8 + (lane >> 2)) * 68 + k0 + (lane & 3)];
                mma8(sacc[ni], a0, a1, a2, a3,
                     __float_as_uint(bp[0]), __float_as_uint(bp[4]));
            }
        }

        // online softmax; write P -> Ps (warp-private rows)
#pragma unroll
        for (int hp = 0; hp < 2; hp++) {
            float mx = -1e30f;
#pragma unroll
            for (int ni = 0; ni < 8; ni++)
                mx = fmaxf(mx, fmaxf(sacc[ni][hp * 2], sacc[ni][hp * 2 + 1]));
            mx = fmaxf(mx, __shfl_xor_sync(0xffffffffu, mx, 1));
            mx = fmaxf(mx, __shfl_xor_sync(0xffffffffu, mx, 2));
            const float mnew = fmaxf(mrow[hp], mx);
            const float corr = __expf(mrow[hp] - mnew);
            mrow[hp] = mnew;
            float rs = 0.f;
            const int prow = rbase + hp * 8;
#pragma unroll
            for (int ni = 0; ni < 8; ni++) {
                const float p0 = __expf(sacc[ni][hp * 2]     - mnew);
                const float p1 = __expf(sacc[ni][hp * 2 + 1] - mnew);
                rs += p0 + p1;
                float2 pv = make_float2(__uint_as_float(f2tf(p0)),
                                        __uint_as_float(f2tf(p1)));
                *reinterpret_cast<float2*>(
                    &Ps[prow * 68 + ni * 8 + (lane & 3) * 2]) = pv;
            }
            rs += __shfl_xor_sync(0xffffffffu, rs, 1);
            rs += __shfl_xor_sync(0xffffffffu, rs, 2);
            lrow[hp] = lrow[hp] * corr + rs;
#pragma unroll
            for (int ni = 0; ni < 8; ni++) {
                o[ni][hp * 2]     *= corr;
                o[ni][hp * 2 + 1] *= corr;
            }
        }
        __syncwarp();   // P rows are warp-private; warp-level visibility is enough

        // O += P @ V   (per warp: m16 x n64, k=64)
#pragma unroll
        for (int ks = 0; ks < 8; ks++) {
            const int k0 = ks * 8;
            const float* ap = &Ps[rbase * 68 + k0 + (lane & 3)];
            const uint32_t a0 = __float_as_uint(ap[0]);
            const uint32_t a1 = __float_as_uint(ap[8 * 68]);
            const uint32_t a2 = __float_as_uint(ap[4]);
            const uint32_t a3 = __float_as_uint(ap[8 * 68 + 4]);
#pragma unroll
            for (int ni = 0; ni < 8; ni++) {
                const float* bp = &Vs[(k0 + (lane & 3)) * 68 + ni * 8 + (lane >> 2)];
                mma8(o[ni], a0, a1, a2, a3,
                     __float_as_uint(bp[0]), __float_as_uint(bp[4 * 68]));
            }
        }
    }

    // epilogue: normalize + write (b, s, h*64+dh)
#pragma unroll
    for (int hp = 0; hp < 2; hp++) {
        const float inv = 1.f / lrow[hp];
        const int row = qt * 128 + rbase + hp * 8;
#pragma unroll
        for (int ni = 0; ni < 8; ni++) {
            const int col = h * 64 + ni * 8 + (lane & 3) * 2;
            float2 st = make_float2(o[ni][hp * 2] * inv, o[ni][hp * 2 + 1] * inv);
            *reinterpret_cast<float2*>(
                g_att + (size_t)(b * SS + row) * DD + col) = st;
        }
    }
}

// ---------------------------------------------------------------------------
// K3: output projection d_out = g_att @ wo
// ---------------------------------------------------------------------------
__global__ __launch_bounds__(256) void proj_mma(
    const float* __restrict__ wo, float* __restrict__ Cout)
{
    __shared__ float As[128 * 36];
    __shared__ float Bs[32 * 132];

    const int tid  = threadIdx.x;
    const int lane = tid & 31;
    const int warp = tid >> 5;
    const int wm = warp >> 2;
    const int wn = warp & 3;
    const int brow = blockIdx.y * 128;
    const int bcol = blockIdx.x * 128;

    float acc[4][4][4];
#pragma unroll
    for (int mi = 0; mi < 4; mi++)
#pragma unroll
        for (int ni = 0; ni < 4; ni++)
#pragma unroll
            for (int f = 0; f < 4; f++) acc[mi][ni][f] = 0.f;

    for (int kk = 0; kk < DD; kk += 32) {
#pragma unroll
        for (int i = 0; i < 4; i++) {
            int idx = tid + i * 256;
            int r = idx >> 3, c4 = (idx & 7) << 2;
            float4 v = *reinterpret_cast<const float4*>(
                g_att + (size_t)(brow + r) * DD + kk + c4);
            *reinterpret_cast<float4*>(&As[r * 36 + c4]) = cvt4(v);
        }
#pragma unroll
        for (int i = 0; i < 4; i++) {
            int idx = tid + i * 256;
            int r = idx >> 5, c4 = (idx & 31) << 2;
            float4 v = *reinterpret_cast<const float4*>(
                wo + (size_t)(kk + r) * DD + bcol + c4);
            *reinterpret_cast<float4*>(&Bs[r * 132 + c4]) = cvt4(v);
        }
        __syncthreads();

#pragma unroll
        for (int ks = 0; ks < 4; ks++) {
            const int k0 = ks * 8;
            uint32_t a[4][4], b[4][2];
            const int ar  = wm * 64 + (lane >> 2);
            const int acl = k0 + (lane & 3);
#pragma unroll
            for (int mi = 0; mi < 4; mi++) {
                const float* p = &As[(ar + mi * 16) * 36 + acl];
                a[mi][0] = __float_as_uint(p[0]);
                a[mi][2] = __float_as_uint(p[4]);
                a[mi][1] = __float_as_uint(p[8 * 36]);
                a[mi][3] = __float_as_uint(p[8 * 36 + 4]);
            }
            const int bc = wn * 32 + (lane >> 2);
            const int br = k0 + (lane & 3);
#pragma unroll
            for (int ni = 0; ni < 4; ni++) {
                const float* p = &Bs[br * 132 + bc + ni * 8];
                b[ni][0] = __float_as_uint(p[0]);
                b[ni][1] = __float_as_uint(p[4 * 132]);
            }
#pragma unroll
            for (int mi = 0; mi < 4; mi++)
#pragma unroll
                for (int ni = 0; ni < 4; ni++)
                    mma8(acc[mi][ni], a[mi][0], a[mi][1], a[mi][2], a[mi][3],
                         b[ni][0], b[ni][1]);
        }
        __syncthreads();
    }

    const int ar = wm * 64 + (lane >> 2);
    const int ac = wn * 32 + (lane & 3) * 2;
#pragma unroll
    for (int mi = 0; mi < 4; mi++)
#pragma unroll
        for (int hp = 0; hp < 2; hp++) {
            const int row = brow + ar + mi * 16 + hp * 8;
#pragma unroll
            for (int ni = 0; ni < 4; ni++) {
                const int col = bcol + ac + ni * 8;
                float2 st = make_float2(acc[mi][ni][hp * 2],
                                        acc[mi][ni][hp * 2 + 1]);
                *reinterpret_cast<float2*>(Cout + (size_t)row * DD + col) = st;
            }
        }
}

// ---------------------------------------------------------------------------
extern "C" void kernel_launch(void* const* d_in, const int* in_sizes, int n_in,
                              void* d_out, int out_size)
{
    const float* x    = (const float*)d_in[0];
    const float* cosT = (const float*)d_in[1];
    const float* sinT = (const float*)d_in[2];
    const float* wq   = (const float*)d_in[3];
    const float* wk   = (const float*)d_in[4];
    const float* wv   = (const float*)d_in[5];
    const float* wo   = (const float*)d_in[6];
    float* out = (float*)d_out;

    cudaFuncSetAttribute(attn_mma,
                         cudaFuncAttributeMaxDynamicSharedMemorySize, ATT_SMEM);

    qkv_mma<<<dim3(DD / 128, MT / 128, 3), 256>>>(x, wq, wk, wv, cosT, sinT);
    attn_mma<<<dim3(SS / 128, HH, BB), 256, ATT_SMEM>>>();
    proj_mma<<<dim3(DD / 128, MT / 128, 1), 256>>>(wo, out);
}

// round 3
// speedup vs baseline: 2.7544x; 1.0616x over previous
#include <cuda_runtime.h>
#include <cstdint>

// ---------------------------------------------------------------------------
// MultiHeadAttention B=2,S=2048,D=1024,H=16,Dh=64 fp32 — TF32 mma + cp.async
// 2-stage pipelines (R3).
// ---------------------------------------------------------------------------

constexpr int BB = 2;
constexpr int SS = 2048;
constexpr int DD = 1024;
constexpr int HH = 16;
constexpr int DH = 64;
constexpr int MT = BB * SS;   // 4096

__device__ float g_q[BB * HH * SS * DH];
__device__ float g_k[BB * HH * SS * DH];
__device__ float g_v[BB * HH * SS * DH];
__device__ float g_att[MT * DD];

__device__ __forceinline__ uint32_t f2tf(float x) {
    uint32_t r;
    asm("cvt.rna.tf32.f32 %0, %1;" : "=r"(r) : "f"(x));
    return r;
}

__device__ __forceinline__ void mma8(float* d, uint32_t a0, uint32_t a1,
                                     uint32_t a2, uint32_t a3,
                                     uint32_t b0, uint32_t b1) {
    asm volatile(
        "mma.sync.aligned.m16n8k8.row.col.f32.tf32.tf32.f32 "
        "{%0,%1,%2,%3}, {%4,%5,%6,%7}, {%8,%9}, {%0,%1,%2,%3};"
        : "+f"(d[0]), "+f"(d[1]), "+f"(d[2]), "+f"(d[3])
        : "r"(a0), "r"(a1), "r"(a2), "r"(a3), "r"(b0), "r"(b1));
}

__device__ __forceinline__ void cp16(uint32_t dst, const void* src) {
    asm volatile("cp.async.cg.shared.global [%0], [%1], 16;"
                 :: "r"(dst), "l"(src));
}
__device__ __forceinline__ void cp_commit() {
    asm volatile("cp.async.commit_group;");
}
template <int N>
__device__ __forceinline__ void cp_wait() {
    asm volatile("cp.async.wait_group %0;" :: "n"(N));
}

__device__ __forceinline__ float4 cvt4(float4 v) {
    float4 o;
    o.x = __uint_as_float(f2tf(v.x));
    o.y = __uint_as_float(f2tf(v.y));
    o.z = __uint_as_float(f2tf(v.z));
    o.w = __uint_as_float(f2tf(v.w));
    return o;
}

// ---------------------------------------------------------------------------
// K1/K3 GEMM geometry: 128x128 block tile, BK=32, 8 warps (2x4), 64x32/warp.
// As stage: [128][36] raw fp32, Bs stage: [32][132]. cvt at fragment read.
// ---------------------------------------------------------------------------
constexpr int AS_ELEM = 128 * 36;   // per stage
constexpr int BS_ELEM = 32 * 132;
constexpr int GEMM_SMEM = 2 * (AS_ELEM + BS_ELEM) * (int)sizeof(float); // 70656

struct GemmCtx {
    float* As;   // base of 2 stages
    float* Bs;
    uint32_t As_s;  // shared addr
    uint32_t Bs_s;
};

__device__ __forceinline__ void gemm_stage(
    const GemmCtx& c, int s, const float* __restrict__ A,
    const float* __restrict__ B, int brow, int bcol, int kk, int tid)
{
#pragma unroll
    for (int i = 0; i < 4; i++) {
        int idx = tid + i * 256;
        int r = idx >> 3, c4 = (idx & 7) << 2;
        cp16(c.As_s + (s * AS_ELEM + r * 36 + c4) * 4,
             A + (size_t)(brow + r) * DD + kk + c4);
    }
#pragma unroll
    for (int i = 0; i < 4; i++) {
        int idx = tid + i * 256;
        int r = idx >> 5, c4 = (idx & 31) << 2;
        cp16(c.Bs_s + (s * BS_ELEM + r * 132 + c4) * 4,
             B + (size_t)(kk + r) * DD + bcol + c4);
    }
    cp_commit();
}

__device__ __forceinline__ void gemm_compute(
    const GemmCtx& c, int s, int lane, int wm, int wn, float acc[4][4][4])
{
    const float* As = c.As + s * AS_ELEM;
    const float* Bs = c.Bs + s * BS_ELEM;
    const int ar = wm * 64 + (lane >> 2);
    const int bc = wn * 32 + (lane >> 2);
#pragma unroll
    for (int ks = 0; ks < 4; ks++) {
        const int k0 = ks * 8;
        uint32_t a[4][4], b[4][2];
        const int acl = k0 + (lane & 3);
#pragma unroll
        for (int mi = 0; mi < 4; mi++) {
            const float* p = &As[(ar + mi * 16) * 36 + acl];
            a[mi][0] = f2tf(p[0]);
            a[mi][2] = f2tf(p[4]);
            a[mi][1] = f2tf(p[8 * 36]);
            a[mi][3] = f2tf(p[8 * 36 + 4]);
        }
        const int br = k0 + (lane & 3);
#pragma unroll
        for (int ni = 0; ni < 4; ni++) {
            const float* p = &Bs[br * 132 + bc + ni * 8];
            b[ni][0] = f2tf(p[0]);
            b[ni][1] = f2tf(p[4 * 132]);
        }
#pragma unroll
        for (int mi = 0; mi < 4; mi++)
#pragma unroll
            for (int ni = 0; ni < 4; ni++)
                mma8(acc[mi][ni], a[mi][0], a[mi][1], a[mi][2], a[mi][3],
                     b[ni][0], b[ni][1]);
    }
}

// ---------------------------------------------------------------------------
// K1: QKV GEMM + RoPE
// ---------------------------------------------------------------------------
__global__ __launch_bounds__(256) void qkv_mma(
    const float* __restrict__ x,
    const float* __restrict__ wq, const float* __restrict__ wk,
    const float* __restrict__ wv,
    const float* __restrict__ cosT, const float* __restrict__ sinT)
{
    extern __shared__ float sm[];
    GemmCtx c;
    c.As = sm;
    c.Bs = sm + 2 * AS_ELEM;
    c.As_s = (uint32_t)__cvta_generic_to_shared(c.As);
    c.Bs_s = (uint32_t)__cvta_generic_to_shared(c.Bs);

    const int mat = blockIdx.z;
    const float* __restrict__ w = (mat == 0) ? wq : (mat == 1) ? wk : wv;
    float* __restrict__ out = (mat == 0) ? g_q : (mat == 1) ? g_k : g_v;

    const int tid  = threadIdx.x;
    const int lane = tid & 31;
    const int warp = tid >> 5;
    const int wm = warp >> 2, wn = warp & 3;
    const int brow = blockIdx.y * 128;
    const int bcol = blockIdx.x * 128;

    float acc[4][4][4];
#pragma unroll
    for (int mi = 0; mi < 4; mi++)
#pragma unroll
        for (int ni = 0; ni < 4; ni++)
#pragma unroll
            for (int f = 0; f < 4; f++) acc[mi][ni][f] = 0.f;

    gemm_stage(c, 0, x, w, brow, bcol, 0, tid);

    constexpr int NCH = DD / 32;  // 32
    for (int i = 0; i < NCH; i++) {
        const int s = i & 1;
        if (i + 1 < NCH) {
            gemm_stage(c, s ^ 1, x, w, brow, bcol, (i + 1) * 32, tid);
            cp_wait<1>();
        } else {
            cp_wait<0>();
        }
        __syncthreads();
        gemm_compute(c, s, lane, wm, wn, acc);
        __syncthreads();
    }

    const int ar = wm * 64 + (lane >> 2);
    const int ac = wn * 32 + (lane & 3) * 2;
#pragma unroll
    for (int mi = 0; mi < 4; mi++) {
#pragma unroll
        for (int hp = 0; hp < 2; hp++) {
            const int row = brow + ar + mi * 16 + hp * 8;
            const int bb = row >> 11;
            const int ss = row & (SS - 1);
#pragma unroll
            for (int ni = 0; ni < 4; ni++) {
                const int col = bcol + ac + ni * 8;
                const int hh = col >> 6;
                const int dh = col & (DH - 1);
                float c0 = acc[mi][ni][hp * 2 + 0];
                float c1 = acc[mi][ni][hp * 2 + 1];
                if (mat < 2) {
                    const int fi = ss * 32 + (dh >> 1);
                    const float cs = cosT[fi], sn = sinT[fi];
                    const float o0 = c0 * cs - c1 * sn;
                    const float o1 = c0 * sn + c1 * cs;
                    c0 = o0; c1 = o1;
                }
                *reinterpret_cast<float2*>(
                    out + ((size_t)(bb * HH + hh) * SS + ss) * DH + dh) =
                    make_float2(c0, c1);
            }
        }
    }
}

// ---------------------------------------------------------------------------
// K2: flash attention.  grid (S/128, H, B), block 256.
// smem: Qs[128][68](tf32), Ks[2][64][68](raw), Vs[2][64][68](raw),
//       Ps[128][68](tf32)
// ---------------------------------------------------------------------------
constexpr int QS_ELEM = 128 * 68;
constexpr int KS_ELEM = 64 * 68;
constexpr int ATT_SMEM = (QS_ELEM + 4 * KS_ELEM + QS_ELEM) * (int)sizeof(float);

__device__ __forceinline__ void attn_stage_kv(
    uint32_t Ks_s, uint32_t Vs_s, int s,
    const float* __restrict__ K, const float* __restrict__ V,
    int kt, int tid)
{
    const float* Kp = K + (size_t)kt * 64 * DH;
    const float* Vp = V + (size_t)kt * 64 * DH;
#pragma unroll
    for (int i = 0; i < 4; i++) {
        int idx = tid + i * 256;
        int r = idx >> 4, c4 = (idx & 15) << 2;
        cp16(Ks_s + (s * KS_ELEM + r * 68 + c4) * 4, Kp + r * DH + c4);
        cp16(Vs_s + (s * KS_ELEM + r * 68 + c4) * 4, Vp + r * DH + c4);
    }
    cp_commit();
}

__global__ __launch_bounds__(256) void attn_mma()
{
    extern __shared__ float sm[];
    float* Qs = sm;                       // [128][68]
    float* Ks = Qs + QS_ELEM;             // [2][64][68]
    float* Vs = Ks + 2 * KS_ELEM;         // [2][64][68]
    float* Ps = Vs + 2 * KS_ELEM;         // [128][68]
    const uint32_t Ks_s = (uint32_t)__cvta_generic_to_shared(Ks);
    const uint32_t Vs_s = (uint32_t)__cvta_generic_to_shared(Vs);

    const int qt = blockIdx.x, h = blockIdx.y, b = blockIdx.z;
    const float* __restrict__ Q = g_q + ((size_t)(b * HH + h) * SS + qt * 128) * DH;
    const float* __restrict__ K = g_k + (size_t)(b * HH + h) * SS * DH;
    const float* __restrict__ V = g_v + (size_t)(b * HH + h) * SS * DH;

    const int tid = threadIdx.x;
    const int lane = tid & 31;
    const int warp = tid >> 5;

    // prologue: start KV stage 0 first, then stage Q while it flies
    attn_stage_kv(Ks_s, Vs_s, 0, K, V, 0, tid);

#pragma unroll
    for (int i = 0; i < 8; i++) {
        int idx = tid + i * 256;
        int r = idx >> 4, c4 = (idx & 15) << 2;
        float4 v = *reinterpret_cast<const float4*>(Q + r * DH + c4);
        v.x *= 0.125f; v.y *= 0.125f; v.z *= 0.125f; v.w *= 0.125f;
        *reinterpret_cast<float4*>(&Qs[r * 68 + c4]) = cvt4(v);
    }

    float mrow[2] = {-1e30f, -1e30f};
    float lrow[2] = {0.f, 0.f};
    float o[8][4];
#pragma unroll
    for (int ni = 0; ni < 8; ni++)
#pragma unroll
        for (int f = 0; f < 4; f++) o[ni][f] = 0.f;

    const int rbase = warp * 16 + (lane >> 2);
    constexpr int NKT = SS / 64;  // 32

    for (int kt = 0; kt < NKT; kt++) {
        const int s = kt & 1;
        if (kt + 1 < NKT) {
            attn_stage_kv(Ks_s, Vs_s, s ^ 1, K, V, kt + 1, tid);
            cp_wait<1>();
        } else {
            cp_wait<0>();
        }
        __syncthreads();

        const float* Kb = Ks + s * KS_ELEM;
        const float* Vb = Vs + s * KS_ELEM;

        // S = Q @ K^T
        float sacc[8][4];
#pragma unroll
        for (int ni = 0; ni < 8; ni++)
#pragma unroll
            for (int f = 0; f < 4; f++) sacc[ni][f] = 0.f;

#pragma unroll
        for (int ks = 0; ks < 8; ks++) {
            const int k0 = ks * 8;
            const float* ap = &Qs[rbase * 68 + k0 + (lane & 3)];
            const uint32_t a0 = __float_as_uint(ap[0]);
            const uint32_t a1 = __float_as_uint(ap[8 * 68]);
            const uint32_t a2 = __float_as_uint(ap[4]);
            const uint32_t a3 = __float_as_uint(ap[8 * 68 + 4]);
#pragma unroll
            for (int ni = 0; ni < 8; ni++) {
                const float* bp = &Kb[(ni * 8 + (lane >> 2)) * 68 + k0 + (lane & 3)];
                mma8(sacc[ni], a0, a1, a2, a3, f2tf(bp[0]), f2tf(bp[4]));
            }
        }

        // online softmax -> Ps (warp-private rows)
#pragma unroll
        for (int hp = 0; hp < 2; hp++) {
            float mx = -1e30f;
#pragma unroll
            for (int ni = 0; ni < 8; ni++)
                mx = fmaxf(mx, fmaxf(sacc[ni][hp * 2], sacc[ni][hp * 2 + 1]));
            mx = fmaxf(mx, __shfl_xor_sync(0xffffffffu, mx, 1));
            mx = fmaxf(mx, __shfl_xor_sync(0xffffffffu, mx, 2));
            const float mnew = fmaxf(mrow[hp], mx);
            const float corr = __expf(mrow[hp] - mnew);
            mrow[hp] = mnew;
            float rs = 0.f;
            const int prow = rbase + hp * 8;
#pragma unroll
            for (int ni = 0; ni < 8; ni++) {
                const float p0 = __expf(sacc[ni][hp * 2]     - mnew);
                const float p1 = __expf(sacc[ni][hp * 2 + 1] - mnew);
                rs += p0 + p1;
                *reinterpret_cast<float2*>(
                    &Ps[prow * 68 + ni * 8 + (lane & 3) * 2]) =
                    make_float2(__uint_as_float(f2tf(p0)),
                                __uint_as_float(f2tf(p1)));
            }
            rs += __shfl_xor_sync(0xffffffffu, rs, 1);
            rs += __shfl_xor_sync(0xffffffffu, rs, 2);
            lrow[hp] = lrow[hp] * corr + rs;
#pragma unroll
            for (int ni = 0; ni < 8; ni++) {
                o[ni][hp * 2]     *= corr;
                o[ni][hp * 2 + 1] *= corr;
            }
        }
        __syncwarp();

        // O += P @ V
#pragma unroll
        for (int ks = 0; ks < 8; ks++) {
            const int k0 = ks * 8;
            const float* ap = &Ps[rbase * 68 + k0 + (lane & 3)];
            const uint32_t a0 = __float_as_uint(ap[0]);
            const uint32_t a1 = __float_as_uint(ap[8 * 68]);
            const uint32_t a2 = __float_as_uint(ap[4]);
            const uint32_t a3 = __float_as_uint(ap[8 * 68 + 4]);
#pragma unroll
            for (int ni = 0; ni < 8; ni++) {
                const float* bp = &Vb[(k0 + (lane & 3)) * 68 + ni * 8 + (lane >> 2)];
                mma8(o[ni], a0, a1, a2, a3, f2tf(bp[0]), f2tf(bp[4 * 68]));
            }
        }
        __syncthreads();
    }

#pragma unroll
    for (int hp = 0; hp < 2; hp++) {
        const float inv = 1.f / lrow[hp];
        const int row = qt * 128 + rbase + hp * 8;
#pragma unroll
        for (int ni = 0; ni < 8; ni++) {
            const int col = h * 64 + ni * 8 + (lane & 3) * 2;
            *reinterpret_cast<float2*>(
                g_att + (size_t)(b * SS + row) * DD + col) =
                make_float2(o[ni][hp * 2] * inv, o[ni][hp * 2 + 1] * inv);
        }
    }
}

// ---------------------------------------------------------------------------
// K3: output projection
// ---------------------------------------------------------------------------
__global__ __launch_bounds__(256) void proj_mma(
    const float* __restrict__ wo, float* __restrict__ Cout)
{
    extern __shared__ float sm[];
    GemmCtx c;
    c.As = sm;
    c.Bs = sm + 2 * AS_ELEM;
    c.As_s = (uint32_t)__cvta_generic_to_shared(c.As);
    c.Bs_s = (uint32_t)__cvta_generic_to_shared(c.Bs);

    const int tid  = threadIdx.x;
    const int lane = tid & 31;
    const int warp = tid >> 5;
    const int wm = warp >> 2, wn = warp & 3;
    const int brow = blockIdx.y * 128;
    const int bcol = blockIdx.x * 128;

    float acc[4][4][4];
#pragma unroll
    for (int mi = 0; mi < 4; mi++)
#pragma unroll
        for (int ni = 0; ni < 4; ni++)
#pragma unroll
            for (int f = 0; f < 4; f++) acc[mi][ni][f] = 0.f;

    static float* att = nullptr;  // device-global base resolved via symbol
    const float* A = g_att;       // direct device-symbol access in device code
    (void)att;

    gemm_stage(c, 0, A, wo, brow, bcol, 0, tid);

    constexpr int NCH = DD / 32;
    for (int i = 0; i < NCH; i++) {
        const int s = i & 1;
        if (i + 1 < NCH) {
            gemm_stage(c, s ^ 1, A, wo, brow, bcol, (i + 1) * 32, tid);
            cp_wait<1>();
        } else {
            cp_wait<0>();
        }
        __syncthreads();
        gemm_compute(c, s, lane, wm, wn, acc);
        __syncthreads();
    }

    const int ar = wm * 64 + (lane >> 2);
    const int ac = wn * 32 + (lane & 3) * 2;
#pragma unroll
    for (int mi = 0; mi < 4; mi++)
#pragma unroll
        for (int hp = 0; hp < 2; hp++) {
            const int row = brow + ar + mi * 16 + hp * 8;
#pragma unroll
            for (int ni = 0; ni < 4; ni++) {
                const int col = bcol + ac + ni * 8;
                *reinterpret_cast<float2*>(Cout + (size_t)row * DD + col) =
                    make_float2(acc[mi][ni][hp * 2], acc[mi][ni][hp * 2 + 1]);
            }
        }
}

// ---------------------------------------------------------------------------
extern "C" void kernel_launch(void* const* d_in, const int* in_sizes, int n_in,
                              void* d_out, int out_size)
{
    const float* x    = (const float*)d_in[0];
    const float* cosT = (const float*)d_in[1];
    const float* sinT = (const float*)d_in[2];
    const float* wq   = (const float*)d_in[3];
    const float* wk   = (const float*)d_in[4];
    const float* wv   = (const float*)d_in[5];
    const float* wo   = (const float*)d_in[6];
    float* out = (float*)d_out;

    static bool attr_set = false;
    if (!attr_set) {
        cudaFuncSetAttribute(qkv_mma,
                             cudaFuncAttributeMaxDynamicSharedMemorySize, GEMM_SMEM);
        cudaFuncSetAttribute(proj_mma,
                             cudaFuncAttributeMaxDynamicSharedMemorySize, GEMM_SMEM);
        cudaFuncSetAttribute(attn_mma,
                             cudaFuncAttributeMaxDynamicSharedMemorySize, ATT_SMEM);
        attr_set = true;
    }

    qkv_mma<<<dim3(DD / 128, MT / 128, 3), 256, GEMM_SMEM>>>(
        x, wq, wk, wv, cosT, sinT);
    attn_mma<<<dim3(SS / 128, HH, BB), 256, ATT_SMEM>>>();
    proj_mma<<<dim3(DD / 128, MT / 128, 1), 256, GEMM_SMEM>>>(wo, out);
}

// round 4
// speedup vs baseline: 2.8062x; 1.0188x over previous
#include <cuda_runtime.h>
#include <cstdint>

// ---------------------------------------------------------------------------
// MultiHeadAttention B=2,S=2048,D=1024,H=16,Dh=64 fp32 — R4:
//  * pre-rounded tf32 inputs (no cvt in hot loops)
//  * 3-stage cp.async pipelines, 1 syncthreads per chunk
// ---------------------------------------------------------------------------

constexpr int BB = 2;
constexpr int SS = 2048;
constexpr int DD = 1024;
constexpr int HH = 16;
constexpr int DH = 64;
constexpr int MT = BB * SS;   // 4096

__device__ float g_q[BB * HH * SS * DH];
__device__ float g_k[BB * HH * SS * DH];
__device__ float g_v[BB * HH * SS * DH];
__device__ float g_att[MT * DD];
// tf32-pre-rounded input copies
__device__ float g_xt[MT * DD];
__device__ float g_wqt[DD * DD];
__device__ float g_wkt[DD * DD];
__device__ float g_wvt[DD * DD];
__device__ float g_wot[DD * DD];

__device__ __forceinline__ uint32_t f2tf(float x) {
    uint32_t r;
    asm("cvt.rna.tf32.f32 %0, %1;" : "=r"(r) : "f"(x));
    return r;
}

__device__ __forceinline__ void mma8(float* d, uint32_t a0, uint32_t a1,
                                     uint32_t a2, uint32_t a3,
                                     uint32_t b0, uint32_t b1) {
    asm volatile(
        "mma.sync.aligned.m16n8k8.row.col.f32.tf32.tf32.f32 "
        "{%0,%1,%2,%3}, {%4,%5,%6,%7}, {%8,%9}, {%0,%1,%2,%3};"
        : "+f"(d[0]), "+f"(d[1]), "+f"(d[2]), "+f"(d[3])
        : "r"(a0), "r"(a1), "r"(a2), "r"(a3), "r"(b0), "r"(b1));
}

__device__ __forceinline__ void cp16(uint32_t dst, const void* src) {
    asm volatile("cp.async.cg.shared.global [%0], [%1], 16;"
                 :: "r"(dst), "l"(src));
}
__device__ __forceinline__ void cp_commit() {
    asm volatile("cp.async.commit_group;");
}
template <int N>
__device__ __forceinline__ void cp_wait() {
    asm volatile("cp.async.wait_group %0;" :: "n"(N));
}

__device__ __forceinline__ float4 cvt4(float4 v) {
    float4 o;
    o.x = __uint_as_float(f2tf(v.x));
    o.y = __uint_as_float(f2tf(v.y));
    o.z = __uint_as_float(f2tf(v.z));
    o.w = __uint_as_float(f2tf(v.w));
    return o;
}

// ---------------------------------------------------------------------------
// K0: pre-round x, wq, wk, wv, wo -> tf32 copies. grid (512, 5), block 256.
// ---------------------------------------------------------------------------
__global__ __launch_bounds__(256) void cvt_inputs(
    const float* __restrict__ x,
    const float* __restrict__ wq, const float* __restrict__ wk,
    const float* __restrict__ wv, const float* __restrict__ wo)
{
    const int z = blockIdx.y;
    const float* src = (z == 0) ? x : (z == 1) ? wq : (z == 2) ? wk
                       : (z == 3) ? wv : wo;
    float* dst = (z == 0) ? g_xt : (z == 1) ? g_wqt : (z == 2) ? g_wkt
                 : (z == 3) ? g_wvt : g_wot;
    const int n4 = ((z == 0) ? MT * DD : DD * DD) >> 2;
    const float4* s4 = reinterpret_cast<const float4*>(src);
    float4* d4 = reinterpret_cast<float4*>(dst);
    for (int i = blockIdx.x * blockDim.x + threadIdx.x; i < n4;
         i += gridDim.x * blockDim.x)
        d4[i] = cvt4(s4[i]);
}

// ---------------------------------------------------------------------------
// GEMM geometry: 128x128 tile, BK=32, 8 warps (2x4), 64x32 per warp.
// 3 cp.async stages. As stage [128][36], Bs stage [32][132].
// ---------------------------------------------------------------------------
constexpr int AS_ELEM = 128 * 36;
constexpr int BS_ELEM = 32 * 132;
constexpr int GEMM_SMEM = 3 * (AS_ELEM + BS_ELEM) * (int)sizeof(float); // 105984

struct GemmCtx {
    float* As;
    float* Bs;
    uint32_t As_s;
    uint32_t Bs_s;
};

__device__ __forceinline__ void gemm_stage(
    const GemmCtx& c, int s, const float* __restrict__ A,
    const float* __restrict__ B, int brow, int bcol, int kk, int tid)
{
#pragma unroll
    for (int i = 0; i < 4; i++) {
        int idx = tid + i * 256;
        int r = idx >> 3, c4 = (idx & 7) << 2;
        cp16(c.As_s + (s * AS_ELEM + r * 36 + c4) * 4,
             A + (size_t)(brow + r) * DD + kk + c4);
    }
#pragma unroll
    for (int i = 0; i < 4; i++) {
        int idx = tid + i * 256;
        int r = idx >> 5, c4 = (idx & 31) << 2;
        cp16(c.Bs_s + (s * BS_ELEM + r * 132 + c4) * 4,
             B + (size_t)(kk + r) * DD + bcol + c4);
    }
    cp_commit();
}

__device__ __forceinline__ void gemm_compute(
    const GemmCtx& c, int s, int lane, int wm, int wn, float acc[4][4][4])
{
    const float* As = c.As + s * AS_ELEM;
    const float* Bs = c.Bs + s * BS_ELEM;
    const int ar = wm * 64 + (lane >> 2);
    const int bc = wn * 32 + (lane >> 2);
#pragma unroll
    for (int ks = 0; ks < 4; ks++) {
        const int k0 = ks * 8;
        uint32_t a[4][4], b[4][2];
        const int acl = k0 + (lane & 3);
#pragma unroll
        for (int mi = 0; mi < 4; mi++) {
            const float* p = &As[(ar + mi * 16) * 36 + acl];
            a[mi][0] = __float_as_uint(p[0]);
            a[mi][2] = __float_as_uint(p[4]);
            a[mi][1] = __float_as_uint(p[8 * 36]);
            a[mi][3] = __float_as_uint(p[8 * 36 + 4]);
        }
        const int br = k0 + (lane & 3);
#pragma unroll
        for (int ni = 0; ni < 4; ni++) {
            const float* p = &Bs[br * 132 + bc + ni * 8];
            b[ni][0] = __float_as_uint(p[0]);
            b[ni][1] = __float_as_uint(p[4 * 132]);
        }
#pragma unroll
        for (int mi = 0; mi < 4; mi++)
#pragma unroll
            for (int ni = 0; ni < 4; ni++)
                mma8(acc[mi][ni], a[mi][0], a[mi][1], a[mi][2], a[mi][3],
                     b[ni][0], b[ni][1]);
    }
}

// 3-stage mainloop: wait -> sync -> stage(i+2) -> compute(i). One sync/chunk.
template <typename EpiF>
__device__ __forceinline__ void gemm_run(
    const GemmCtx& c, const float* __restrict__ A, const float* __restrict__ B,
    int brow, int bcol, int tid, EpiF epi)
{
    const int lane = tid & 31;
    const int warp = tid >> 5;
    const int wm = warp >> 2, wn = warp & 3;

    float acc[4][4][4];
#pragma unroll
    for (int mi = 0; mi < 4; mi++)
#pragma unroll
        for (int ni = 0; ni < 4; ni++)
#pragma unroll
            for (int f = 0; f < 4; f++) acc[mi][ni][f] = 0.f;

    constexpr int NCH = DD / 32;  // 32
    gemm_stage(c, 0, A, B, brow, bcol, 0, tid);
    gemm_stage(c, 1, A, B, brow, bcol, 32, tid);

    for (int i = 0; i < NCH; i++) {
        if (i + 1 < NCH) cp_wait<1>(); else cp_wait<0>();
        __syncthreads();
        if (i + 2 < NCH)
            gemm_stage(c, (i + 2) % 3, A, B, brow, bcol, (i + 2) * 32, tid);
        gemm_compute(c, i % 3, lane, wm, wn, acc);
    }
    epi(acc, lane, wm, wn);
}

// ---------------------------------------------------------------------------
// K1: QKV GEMM + RoPE (pre-rounded inputs; rounded outputs; q pre-scaled)
// ---------------------------------------------------------------------------
__global__ __launch_bounds__(256, 2) void qkv_mma(
    const float* __restrict__ cosT, const float* __restrict__ sinT)
{
    extern __shared__ float sm[];
    GemmCtx c;
    c.As = sm;
    c.Bs = sm + 3 * AS_ELEM;
    c.As_s = (uint32_t)__cvta_generic_to_shared(c.As);
    c.Bs_s = (uint32_t)__cvta_generic_to_shared(c.Bs);

    const int mat = blockIdx.z;
    const float* __restrict__ w =
        (mat == 0) ? g_wqt : (mat == 1) ? g_wkt : g_wvt;
    float* __restrict__ out = (mat == 0) ? g_q : (mat == 1) ? g_k : g_v;

    const int tid = threadIdx.x;
    const int brow = blockIdx.y * 128;
    const int bcol = blockIdx.x * 128;

    gemm_run(c, g_xt, w, brow, bcol, tid,
        [&](float acc[4][4][4], int lane, int wm, int wn) {
            const int ar = wm * 64 + (lane >> 2);
            const int ac = wn * 32 + (lane & 3) * 2;
#pragma unroll
            for (int mi = 0; mi < 4; mi++) {
#pragma unroll
                for (int hp = 0; hp < 2; hp++) {
                    const int row = brow + ar + mi * 16 + hp * 8;
                    const int bb = row >> 11;
                    const int ss = row & (SS - 1);
#pragma unroll
                    for (int ni = 0; ni < 4; ni++) {
                        const int col = bcol + ac + ni * 8;
                        const int hh = col >> 6;
                        const int dh = col & (DH - 1);
                        float c0 = acc[mi][ni][hp * 2 + 0];
                        float c1 = acc[mi][ni][hp * 2 + 1];
                        if (mat < 2) {
                            const int fi = ss * 32 + (dh >> 1);
                            const float cs = cosT[fi], sn = sinT[fi];
                            const float o0 = c0 * cs - c1 * sn;
                            const float o1 = c0 * sn + c1 * cs;
                            c0 = o0; c1 = o1;
                        }
                        if (mat == 0) { c0 *= 0.125f; c1 *= 0.125f; }
                        *reinterpret_cast<float2*>(
                            out + ((size_t)(bb * HH + hh) * SS + ss) * DH + dh) =
                            make_float2(__uint_as_float(f2tf(c0)),
                                        __uint_as_float(f2tf(c1)));
                    }
                }
            }
        });
}

// ---------------------------------------------------------------------------
// K2: flash attention. grid (S/128, H, B), block 256 (8 warps x 16 rows).
// smem: Qs[128][68], Ks[3][64][68], Vs[3][64][68], Ps[128][68] = 174080 B.
// ---------------------------------------------------------------------------
constexpr int QS_ELEM = 128 * 68;
constexpr int KS_ELEM = 64 * 68;
constexpr int ATT_SMEM =
    (2 * QS_ELEM + 6 * KS_ELEM) * (int)sizeof(float);  // 174080

__device__ __forceinline__ void attn_stage_kv(
    uint32_t Ks_s, uint32_t Vs_s, int s,
    const float* __restrict__ K, const float* __restrict__ V,
    int kt, int tid)
{
    const float* Kp = K + (size_t)kt * 64 * DH;
    const float* Vp = V + (size_t)kt * 64 * DH;
#pragma unroll
    for (int i = 0; i < 4; i++) {
        int idx = tid + i * 256;
        int r = idx >> 4, c4 = (idx & 15) << 2;
        cp16(Ks_s + (s * KS_ELEM + r * 68 + c4) * 4, Kp + r * DH + c4);
        cp16(Vs_s + (s * KS_ELEM + r * 68 + c4) * 4, Vp + r * DH + c4);
    }
    cp_commit();
}

__global__ __launch_bounds__(256) void attn_mma()
{
    extern __shared__ float sm[];
    float* Qs = sm;                       // [128][68]
    float* Ks = Qs + QS_ELEM;             // [3][64][68]
    float* Vs = Ks + 3 * KS_ELEM;         // [3][64][68]
    float* Ps = Vs + 3 * KS_ELEM;         // [128][68]
    const uint32_t Qs_s = (uint32_t)__cvta_generic_to_shared(Qs);
    const uint32_t Ks_s = (uint32_t)__cvta_generic_to_shared(Ks);
    const uint32_t Vs_s = (uint32_t)__cvta_generic_to_shared(Vs);

    const int qt = blockIdx.x, h = blockIdx.y, b = blockIdx.z;
    const float* __restrict__ Q = g_q + ((size_t)(b * HH + h) * SS + qt * 128) * DH;
    const float* __restrict__ K = g_k + (size_t)(b * HH + h) * SS * DH;
    const float* __restrict__ V = g_v + (size_t)(b * HH + h) * SS * DH;

    const int tid = threadIdx.x;
    const int lane = tid & 31;
    const int warp = tid >> 5;

    // prologue: KV0 (g0), Q (g1, already scaled+rounded), KV1 (g2)
    attn_stage_kv(Ks_s, Vs_s, 0, K, V, 0, tid);
#pragma unroll
    for (int i = 0; i < 8; i++) {
        int idx = tid + i * 256;
        int r = idx >> 4, c4 = (idx & 15) << 2;
        cp16(Qs_s + (r * 68 + c4) * 4, Q + r * DH + c4);
    }
    cp_commit();
    attn_stage_kv(Ks_s, Vs_s, 1, K, V, 1, tid);

    float mrow[2] = {-1e30f, -1e30f};
    float lrow[2] = {0.f, 0.f};
    float o[8][4];
#pragma unroll
    for (int ni = 0; ni < 8; ni++)
#pragma unroll
        for (int f = 0; f < 4; f++) o[ni][f] = 0.f;

    const int rbase = warp * 16 + (lane >> 2);
    constexpr int NKT = SS / 64;  // 32

    for (int kt = 0; kt < NKT; kt++) {
        if (kt + 1 < NKT) cp_wait<1>(); else cp_wait<0>();
        __syncthreads();
        if (kt + 2 < NKT)
            attn_stage_kv(Ks_s, Vs_s, (kt + 2) % 3, K, V, kt + 2, tid);

        const float* Kb = Ks + (kt % 3) * KS_ELEM;
        const float* Vb = Vs + (kt % 3) * KS_ELEM;

        // S = Q @ K^T  (m16 x n64 x k64 per warp)
        float sacc[8][4];
#pragma unroll
        for (int ni = 0; ni < 8; ni++)
#pragma unroll
            for (int f = 0; f < 4; f++) sacc[ni][f] = 0.f;

#pragma unroll
        for (int ks = 0; ks < 8; ks++) {
            const int k0 = ks * 8;
            const float* ap = &Qs[rbase * 68 + k0 + (lane & 3)];
            const uint32_t a0 = __float_as_uint(ap[0]);
            const uint32_t a1 = __float_as_uint(ap[8 * 68]);
            const uint32_t a2 = __float_as_uint(ap[4]);
            const uint32_t a3 = __float_as_uint(ap[8 * 68 + 4]);
#pragma unroll
            for (int ni = 0; ni < 8; ni++) {
                const float* bp = &Kb[(ni * 8 + (lane >> 2)) * 68 + k0 + (lane & 3)];
                mma8(sacc[ni], a0, a1, a2, a3,
                     __float_as_uint(bp[0]), __float_as_uint(bp[4]));
            }
        }

        // online softmax -> Ps (warp-private rows)
#pragma unroll
        for (int hp = 0; hp < 2; hp++) {
            float mx = -1e30f;
#pragma unroll
            for (int ni = 0; ni < 8; ni++)
                mx = fmaxf(mx, fmaxf(sacc[ni][hp * 2], sacc[ni][hp * 2 + 1]));
            mx = fmaxf(mx, __shfl_xor_sync(0xffffffffu, mx, 1));
            mx = fmaxf(mx, __shfl_xor_sync(0xffffffffu, mx, 2));
            const float mnew = fmaxf(mrow[hp], mx);
            const float corr = __expf(mrow[hp] - mnew);
            mrow[hp] = mnew;
            float rs = 0.f;
            const int prow = rbase + hp * 8;
#pragma unroll
            for (int ni = 0; ni < 8; ni++) {
                const float p0 = __expf(sacc[ni][hp * 2]     - mnew);
                const float p1 = __expf(sacc[ni][hp * 2 + 1] - mnew);
                rs += p0 + p1;
                *reinterpret_cast<float2*>(
                    &Ps[prow * 68 + ni * 8 + (lane & 3) * 2]) =
                    make_float2(__uint_as_float(f2tf(p0)),
                                __uint_as_float(f2tf(p1)));
            }
            rs += __shfl_xor_sync(0xffffffffu, rs, 1);
            rs += __shfl_xor_sync(0xffffffffu, rs, 2);
            lrow[hp] = lrow[hp] * corr + rs;
#pragma unroll
            for (int ni = 0; ni < 8; ni++) {
                o[ni][hp * 2]     *= corr;
                o[ni][hp * 2 + 1] *= corr;
            }
        }
        __syncwarp();

        // O += P @ V
#pragma unroll
        for (int ks = 0; ks < 8; ks++) {
            const int k0 = ks * 8;
            const float* ap = &Ps[rbase * 68 + k0 + (lane & 3)];
            const uint32_t a0 = __float_as_uint(ap[0]);
            const uint32_t a1 = __float_as_uint(ap[8 * 68]);
            const uint32_t a2 = __float_as_uint(ap[4]);
            const uint32_t a3 = __float_as_uint(ap[8 * 68 + 4]);
#pragma unroll
            for (int ni = 0; ni < 8; ni++) {
                const float* bp = &Vb[(k0 + (lane & 3)) * 68 + ni * 8 + (lane >> 2)];
                mma8(o[ni], a0, a1, a2, a3,
                     __float_as_uint(bp[0]), __float_as_uint(bp[4 * 68]));
            }
        }
    }

    // epilogue: normalize + round + write (b, s, h*64+dh)
#pragma unroll
    for (int hp = 0; hp < 2; hp++) {
        const float inv = 1.f / lrow[hp];
        const int row = qt * 128 + rbase + hp * 8;
#pragma unroll
        for (int ni = 0; ni < 8; ni++) {
            const int col = h * 64 + ni * 8 + (lane & 3) * 2;
            *reinterpret_cast<float2*>(
                g_att + (size_t)(b * SS + row) * DD + col) =
                make_float2(__uint_as_float(f2tf(o[ni][hp * 2] * inv)),
                            __uint_as_float(f2tf(o[ni][hp * 2 + 1] * inv)));
        }
    }
}

// ---------------------------------------------------------------------------
// K3: output projection (pre-rounded g_att & wo)
// ---------------------------------------------------------------------------
__global__ __launch_bounds__(256, 2) void proj_mma(float* __restrict__ Cout)
{
    extern __shared__ float sm[];
    GemmCtx c;
    c.As = sm;
    c.Bs = sm + 3 * AS_ELEM;
    c.As_s = (uint32_t)__cvta_generic_to_shared(c.As);
    c.Bs_s = (uint32_t)__cvta_generic_to_shared(c.Bs);

    const int tid = threadIdx.x;
    const int brow = blockIdx.y * 128;
    const int bcol = blockIdx.x * 128;

    gemm_run(c, g_att, g_wot, brow, bcol, tid,
        [&](float acc[4][4][4], int lane, int wm, int wn) {
            const int ar = wm * 64 + (lane >> 2);
            const int ac = wn * 32 + (lane & 3) * 2;
#pragma unroll
            for (int mi = 0; mi < 4; mi++)
#pragma unroll
                for (int hp = 0; hp < 2; hp++) {
                    const int row = brow + ar + mi * 16 + hp * 8;
#pragma unroll
                    for (int ni = 0; ni < 4; ni++) {
                        const int col = bcol + ac + ni * 8;
                        *reinterpret_cast<float2*>(
                            Cout + (size_t)row * DD + col) =
                            make_float2(acc[mi][ni][hp * 2],
                                        acc[mi][ni][hp * 2 + 1]);
                    }
                }
        });
}

// ---------------------------------------------------------------------------
extern "C" void kernel_launch(void* const* d_in, const int* in_sizes, int n_in,
                              void* d_out, int out_size)
{
    const float* x    = (const float*)d_in[0];
    const float* cosT = (const float*)d_in[1];
    const float* sinT = (const float*)d_in[2];
    const float* wq   = (const float*)d_in[3];
    const float* wk   = (const float*)d_in[4];
    const float* wv   = (const float*)d_in[5];
    const float* wo   = (const float*)d_in[6];
    float* out = (float*)d_out;

    static bool attr_set = false;
    if (!attr_set) {
        cudaFuncSetAttribute(qkv_mma,
                             cudaFuncAttributeMaxDynamicSharedMemorySize, GEMM_SMEM);
        cudaFuncSetAttribute(proj_mma,
                             cudaFuncAttributeMaxDynamicSharedMemorySize, GEMM_SMEM);
        cudaFuncSetAttribute(attn_mma,
                             cudaFuncAttributeMaxDynamicSharedMemorySize, ATT_SMEM);
        attr_set = true;
    }

    cvt_inputs<<<dim3(512, 5), 256>>>(x, wq, wk, wv, wo);
    qkv_mma<<<dim3(DD / 128, MT / 128, 3), 256, GEMM_SMEM>>>(cosT, sinT);
    attn_mma<<<dim3(SS / 128, HH, BB), 256, ATT_SMEM>>>();
    proj_mma<<<dim3(DD / 128, MT / 128, 1), 256, GEMM_SMEM>>>(out);
}

// round 6
// speedup vs baseline: 3.5932x; 1.2804x over previous
#include <cuda_runtime.h>
#include <cstdint>

// ---------------------------------------------------------------------------
// MultiHeadAttention B=2,S=2048,D=1024,H=16,Dh=64 fp32 — R6:
//  mma.sync tf32 (tcgen05 unavailable: harness emits compute_103 PTX).
//  * GEMMs: 64x64 warp tile (LDS/mma 1.0), conflict-free Bs stride 136
//  * Attention: 256 q-rows/block, 8 warps m32n64, stride 72, 2-stage KV
// ---------------------------------------------------------------------------

constexpr int BB = 2;
constexpr int SS = 2048;
constexpr int DD = 1024;
constexpr int HH = 16;
constexpr int DH = 64;
constexpr int MT = BB * SS;   // 4096

__device__ float g_q[BB * HH * SS * DH];
__device__ float g_k[BB * HH * SS * DH];
__device__ float g_v[BB * HH * SS * DH];
__device__ float g_att[MT * DD];
__device__ float g_xt[MT * DD];
__device__ float g_wqt[DD * DD];
__device__ float g_wkt[DD * DD];
__device__ float g_wvt[DD * DD];
__device__ float g_wot[DD * DD];

__device__ __forceinline__ uint32_t f2tf(float x) {
    uint32_t r;
    asm("cvt.rna.tf32.f32 %0, %1;" : "=r"(r) : "f"(x));
    return r;
}
__device__ __forceinline__ void mma8(float* d, uint32_t a0, uint32_t a1,
                                     uint32_t a2, uint32_t a3,
                                     uint32_t b0, uint32_t b1) {
    asm volatile(
        "mma.sync.aligned.m16n8k8.row.col.f32.tf32.tf32.f32 "
        "{%0,%1,%2,%3}, {%4,%5,%6,%7}, {%8,%9}, {%0,%1,%2,%3};"
        : "+f"(d[0]), "+f"(d[1]), "+f"(d[2]), "+f"(d[3])
        : "r"(a0), "r"(a1), "r"(a2), "r"(a3), "r"(b0), "r"(b1));
}
__device__ __forceinline__ void cp16(uint32_t dst, const void* src) {
    asm volatile("cp.async.cg.shared.global [%0], [%1], 16;"
                 :: "r"(dst), "l"(src));
}
__device__ __forceinline__ void cp_commit() {
    asm volatile("cp.async.commit_group;");
}
template <int N>
__device__ __forceinline__ void cp_wait() {
    asm volatile("cp.async.wait_group %0;" :: "n"(N));
}
__device__ __forceinline__ float4 cvt4(float4 v) {
    float4 o;
    o.x = __uint_as_float(f2tf(v.x));
    o.y = __uint_as_float(f2tf(v.y));
    o.z = __uint_as_float(f2tf(v.z));
    o.w = __uint_as_float(f2tf(v.w));
    return o;
}

// ---------------------------------------------------------------------------
// K0: pre-round x, wq, wk, wv, wo.
// ---------------------------------------------------------------------------
__global__ __launch_bounds__(256) void cvt_inputs(
    const float* __restrict__ x,
    const float* __restrict__ wq, const float* __restrict__ wk,
    const float* __restrict__ wv, const float* __restrict__ wo)
{
    const int z = blockIdx.y;
    const float* src = (z == 0) ? x : (z == 1) ? wq : (z == 2) ? wk
                       : (z == 3) ? wv : wo;
    float* dst = (z == 0) ? g_xt : (z == 1) ? g_wqt : (z == 2) ? g_wkt
                 : (z == 3) ? g_wvt : g_wot;
    const int n4 = ((z == 0) ? MT * DD : DD * DD) >> 2;
    const float4* s4 = reinterpret_cast<const float4*>(src);
    float4* d4 = reinterpret_cast<float4*>(dst);
    for (int i = blockIdx.x * blockDim.x + threadIdx.x; i < n4;
         i += gridDim.x * blockDim.x)
        d4[i] = cvt4(s4[i]);
}

// ---------------------------------------------------------------------------
// GEMM: 128x128 tile, BK=32, 4 warps (2x2), 64x64 per warp, 3-stage cp.async.
// As [128][36] (bank 4r+q: conflict-free), Bs [32][136] (bank 8q: CF).
// ---------------------------------------------------------------------------
constexpr int AS_ELEM = 128 * 36;   // 4608
constexpr int BS_ELEM = 32 * 136;   // 4352
constexpr int GEMM_SMEM = 3 * (AS_ELEM + BS_ELEM) * (int)sizeof(float); // 107520

__device__ __forceinline__ void gemm_stage(
    uint32_t As_s, uint32_t Bs_s, int s, const float* __restrict__ A,
    const float* __restrict__ B, int brow, int bcol, int kk, int tid)
{
#pragma unroll
    for (int i = 0; i < 8; i++) {
        int idx = tid + (i << 7);
        int r = idx >> 3, c4 = (idx & 7) << 2;
        cp16(As_s + (s * AS_ELEM + r * 36 + c4) * 4,
             A + (size_t)(brow + r) * DD + kk + c4);
    }
#pragma unroll
    for (int i = 0; i < 8; i++) {
        int idx = tid + (i << 7);
        int r = idx >> 5, c4 = (idx & 31) << 2;
        cp16(Bs_s + (s * BS_ELEM + r * 136 + c4) * 4,
             B + (size_t)(kk + r) * DD + bcol + c4);
    }
    cp_commit();
}

__device__ __forceinline__ void gemm_compute(
    const float* As, const float* Bs, int lane, int wm, int wn,
    float acc[4][8][4])
{
    const int ar = wm * 64 + (lane >> 2);
    const int bc = wn * 64 + (lane >> 2);
#pragma unroll
    for (int ks = 0; ks < 4; ks++) {
        const int k0 = ks * 8;
        uint32_t a[4][4], b[8][2];
        const int acl = k0 + (lane & 3);
#pragma unroll
        for (int mi = 0; mi < 4; mi++) {
            const float* p = &As[(ar + mi * 16) * 36 + acl];
            a[mi][0] = __float_as_uint(p[0]);
            a[mi][2] = __float_as_uint(p[4]);
            a[mi][1] = __float_as_uint(p[8 * 36]);
            a[mi][3] = __float_as_uint(p[8 * 36 + 4]);
        }
        const int br = k0 + (lane & 3);
#pragma unroll
        for (int ni = 0; ni < 8; ni++) {
            const float* p = &Bs[br * 136 + bc + ni * 8];
            b[ni][0] = __float_as_uint(p[0]);
            b[ni][1] = __float_as_uint(p[4 * 136]);
        }
#pragma unroll
        for (int mi = 0; mi < 4; mi++)
#pragma unroll
            for (int ni = 0; ni < 8; ni++)
                mma8(acc[mi][ni], a[mi][0], a[mi][1], a[mi][2], a[mi][3],
                     b[ni][0], b[ni][1]);
    }
}

template <typename EpiF>
__device__ __forceinline__ void gemm_run(
    float* sm, const float* __restrict__ A, const float* __restrict__ B,
    int brow, int bcol, EpiF epi)
{
    const uint32_t As_s = (uint32_t)__cvta_generic_to_shared(sm);
    const uint32_t Bs_s = (uint32_t)__cvta_generic_to_shared(sm + 3 * AS_ELEM);
    const float* AsB = sm;
    const float* BsB = sm + 3 * AS_ELEM;

    const int tid = threadIdx.x;
    const int lane = tid & 31;
    const int warp = tid >> 5;
    const int wm = warp >> 1, wn = warp & 1;

    float acc[4][8][4];
#pragma unroll
    for (int mi = 0; mi < 4; mi++)
#pragma unroll
        for (int ni = 0; ni < 8; ni++)
#pragma unroll
            for (int f = 0; f < 4; f++) acc[mi][ni][f] = 0.f;

    constexpr int NCH = DD / 32;  // 32
    gemm_stage(As_s, Bs_s, 0, A, B, brow, bcol, 0, tid);
    gemm_stage(As_s, Bs_s, 1, A, B, brow, bcol, 32, tid);

    for (int i = 0; i < NCH; i++) {
        if (i + 1 < NCH) cp_wait<1>(); else cp_wait<0>();
        __syncthreads();
        if (i + 2 < NCH)
            gemm_stage(As_s, Bs_s, (i + 2) % 3, A, B, brow, bcol,
                       (i + 2) * 32, tid);
        gemm_compute(AsB + (i % 3) * AS_ELEM, BsB + (i % 3) * BS_ELEM,
                     lane, wm, wn, acc);
    }
    epi(acc, lane, wm, wn);
}

// ---------------------------------------------------------------------------
// K1: QKV GEMM + RoPE
// ---------------------------------------------------------------------------
__global__ __launch_bounds__(128, 2) void qkv_mma(
    const float* __restrict__ cosT, const float* __restrict__ sinT)
{
    extern __shared__ float sm[];
    const int mat = blockIdx.z;
    const float* __restrict__ w =
        (mat == 0) ? g_wqt : (mat == 1) ? g_wkt : g_wvt;
    float* __restrict__ out = (mat == 0) ? g_q : (mat == 1) ? g_k : g_v;
    const int brow = blockIdx.y * 128;
    const int bcol = blockIdx.x * 128;

    gemm_run(sm, g_xt, w, brow, bcol,
        [&](float acc[4][8][4], int lane, int wm, int wn) {
            const int ar = wm * 64 + (lane >> 2);
            const int ac = wn * 64 + (lane & 3) * 2;
#pragma unroll
            for (int mi = 0; mi < 4; mi++) {
#pragma unroll
                for (int hp = 0; hp < 2; hp++) {
                    const int row = brow + ar + mi * 16 + hp * 8;
                    const int bb = row >> 11;
                    const int ss = row & (SS - 1);
#pragma unroll
                    for (int ni = 0; ni < 8; ni++) {
                        const int col = bcol + ac + ni * 8;
                        const int hh = col >> 6;
                        const int dh = col & (DH - 1);
                        float c0 = acc[mi][ni][hp * 2 + 0];
                        float c1 = acc[mi][ni][hp * 2 + 1];
                        if (mat < 2) {
                            const int fi = ss * 32 + (dh >> 1);
                            const float cs = cosT[fi], sn = sinT[fi];
                            const float o0 = c0 * cs - c1 * sn;
                            const float o1 = c0 * sn + c1 * cs;
                            c0 = o0; c1 = o1;
                        }
                        if (mat == 0) { c0 *= 0.125f; c1 *= 0.125f; }
                        *reinterpret_cast<float2*>(
                            out + ((size_t)(bb * HH + hh) * SS + ss) * DH + dh) =
                            make_float2(__uint_as_float(f2tf(c0)),
                                        __uint_as_float(f2tf(c1)));
                    }
                }
            }
        });
}

// ---------------------------------------------------------------------------
// K3: output projection
// ---------------------------------------------------------------------------
__global__ __launch_bounds__(128, 2) void proj_mma(float* __restrict__ Cout)
{
    extern __shared__ float sm[];
    const int brow = blockIdx.y * 128;
    const int bcol = blockIdx.x * 128;

    gemm_run(sm, g_att, g_wot, brow, bcol,
        [&](float acc[4][8][4], int lane, int wm, int wn) {
            const int ar = wm * 64 + (lane >> 2);
            const int ac = wn * 64 + (lane & 3) * 2;
#pragma unroll
            for (int mi = 0; mi < 4; mi++)
#pragma unroll
                for (int hp = 0; hp < 2; hp++) {
                    const int row = brow + ar + mi * 16 + hp * 8;
#pragma unroll
                    for (int ni = 0; ni < 8; ni++) {
                        const int col = bcol + ac + ni * 8;
                        *reinterpret_cast<float2*>(
                            Cout + (size_t)row * DD + col) =
                            make_float2(acc[mi][ni][hp * 2],
                                        acc[mi][ni][hp * 2 + 1]);
                    }
                }
        });
}

// ---------------------------------------------------------------------------
// K2: flash attention. grid (S/256, H, B), block 256 (8 warps x 32 rows,
// m32n64 per warp). smem stride 72 (conflict-free fragment loads).
// Qs[256][72], Ks[2][64][72], Vs[2][64][72], Ps[256][72] = 221184 B.
// ---------------------------------------------------------------------------
constexpr int AST = 72;
constexpr int QS_ELEM = 256 * AST;
constexpr int KS_ELEM = 64 * AST;
constexpr int ATT_SMEM = (2 * QS_ELEM + 4 * KS_ELEM) * (int)sizeof(float);

__device__ __forceinline__ void attn_stage_kv(
    uint32_t Ks_s, uint32_t Vs_s, int s,
    const float* __restrict__ K, const float* __restrict__ V,
    int kt, int tid)
{
    const float* Kp = K + (size_t)kt * 64 * DH;
    const float* Vp = V + (size_t)kt * 64 * DH;
#pragma unroll
    for (int i = 0; i < 4; i++) {
        int idx = tid + (i << 8);
        int r = idx >> 4, c4 = (idx & 15) << 2;
        cp16(Ks_s + (s * KS_ELEM + r * AST + c4) * 4, Kp + r * DH + c4);
        cp16(Vs_s + (s * KS_ELEM + r * AST + c4) * 4, Vp + r * DH + c4);
    }
    cp_commit();
}

__global__ __launch_bounds__(256, 1) void attn_mma()
{
    extern __shared__ float sm[];
    float* Qs = sm;                       // [256][72]
    float* Ks = Qs + QS_ELEM;             // [2][64][72]
    float* Vs = Ks + 2 * KS_ELEM;         // [2][64][72]
    float* Ps = Vs + 2 * KS_ELEM;         // [256][72]
    const uint32_t Qs_s = (uint32_t)__cvta_generic_to_shared(Qs);
    const uint32_t Ks_s = (uint32_t)__cvta_generic_to_shared(Ks);
    const uint32_t Vs_s = (uint32_t)__cvta_generic_to_shared(Vs);

    const int qt = blockIdx.x, h = blockIdx.y, b = blockIdx.z;
    const float* __restrict__ Q = g_q + ((size_t)(b * HH + h) * SS + qt * 256) * DH;
    const float* __restrict__ K = g_k + (size_t)(b * HH + h) * SS * DH;
    const float* __restrict__ V = g_v + (size_t)(b * HH + h) * SS * DH;

    const int tid = threadIdx.x;
    const int lane = tid & 31;
    const int warp = tid >> 5;

    // prologue: KV0 (grp0), Q (grp1), KV1 (grp2)
    attn_stage_kv(Ks_s, Vs_s, 0, K, V, 0, tid);
#pragma unroll
    for (int i = 0; i < 16; i++) {
        int idx = tid + (i << 8);
        int r = idx >> 4, c4 = (idx & 15) << 2;
        cp16(Qs_s + (r * AST + c4) * 4, Q + r * DH + c4);
    }
    cp_commit();
    attn_stage_kv(Ks_s, Vs_s, 1, K, V, 1, tid);

    float mrow[2][2], lrow[2][2];
    float o[2][8][4];
#pragma unroll
    for (int mi = 0; mi < 2; mi++)
#pragma unroll
        for (int hp = 0; hp < 2; hp++) {
            mrow[mi][hp] = -1e30f;
            lrow[mi][hp] = 0.f;
        }
#pragma unroll
    for (int mi = 0; mi < 2; mi++)
#pragma unroll
        for (int ni = 0; ni < 8; ni++)
#pragma unroll
            for (int f = 0; f < 4; f++) o[mi][ni][f] = 0.f;

    const int rbase = warp * 32 + (lane >> 2);
    constexpr int NKT = SS / 64;  // 32

    for (int kt = 0; kt < NKT; kt++) {
        if (kt + 1 < NKT) cp_wait<1>(); else cp_wait<0>();
        __syncthreads();

        const int s = kt & 1;
        const float* Kb = Ks + s * KS_ELEM;
        const float* Vb = Vs + s * KS_ELEM;

        // S = Q @ K^T  (m32 x n64 x k64 per warp)
        float sacc[2][8][4];
#pragma unroll
        for (int mi = 0; mi < 2; mi++)
#pragma unroll
            for (int ni = 0; ni < 8; ni++)
#pragma unroll
                for (int f = 0; f < 4; f++) sacc[mi][ni][f] = 0.f;

#pragma unroll
        for (int ks = 0; ks < 8; ks++) {
            const int k0 = ks * 8;
            uint32_t a[2][4];
#pragma unroll
            for (int mi = 0; mi < 2; mi++) {
                const float* ap = &Qs[(rbase + mi * 16) * AST + k0 + (lane & 3)];
                a[mi][0] = __float_as_uint(ap[0]);
                a[mi][1] = __float_as_uint(ap[8 * AST]);
                a[mi][2] = __float_as_uint(ap[4]);
                a[mi][3] = __float_as_uint(ap[8 * AST + 4]);
            }
#pragma unroll
            for (int ni = 0; ni < 8; ni++) {
                const float* bp = &Kb[(ni * 8 + (lane >> 2)) * AST + k0 + (lane & 3)];
                const uint32_t b0 = __float_as_uint(bp[0]);
                const uint32_t b1 = __float_as_uint(bp[4]);
#pragma unroll
                for (int mi = 0; mi < 2; mi++)
                    mma8(sacc[mi][ni], a[mi][0], a[mi][1], a[mi][2], a[mi][3],
                         b0, b1);
            }
        }

        // online softmax -> Ps
#pragma unroll
        for (int mi = 0; mi < 2; mi++) {
#pragma unroll
            for (int hp = 0; hp < 2; hp++) {
                float mx = -1e30f;
#pragma unroll
                for (int ni = 0; ni < 8; ni++)
                    mx = fmaxf(mx, fmaxf(sacc[mi][ni][hp * 2],
                                         sacc[mi][ni][hp * 2 + 1]));
                mx = fmaxf(mx, __shfl_xor_sync(0xffffffffu, mx, 1));
                mx = fmaxf(mx, __shfl_xor_sync(0xffffffffu, mx, 2));
                const float mnew = fmaxf(mrow[mi][hp], mx);
                const float corr = __expf(mrow[mi][hp] - mnew);
                mrow[mi][hp] = mnew;
                float rs = 0.f;
                const int prow = rbase + mi * 16 + hp * 8;
#pragma unroll
                for (int ni = 0; ni < 8; ni++) {
                    const float p0 = __expf(sacc[mi][ni][hp * 2]     - mnew);
                    const float p1 = __expf(sacc[mi][ni][hp * 2 + 1] - mnew);
                    rs += p0 + p1;
                    *reinterpret_cast<float2*>(
                        &Ps[prow * AST + ni * 8 + (lane & 3) * 2]) =
                        make_float2(__uint_as_float(f2tf(p0)),
                                    __uint_as_float(f2tf(p1)));
                }
                rs += __shfl_xor_sync(0xffffffffu, rs, 1);
                rs += __shfl_xor_sync(0xffffffffu, rs, 2);
                lrow[mi][hp] = lrow[mi][hp] * corr + rs;
#pragma unroll
                for (int ni = 0; ni < 8; ni++) {
                    o[mi][ni][hp * 2]     *= corr;
                    o[mi][ni][hp * 2 + 1] *= corr;
                }
            }
        }
        __syncwarp();

        // O += P @ V
#pragma unroll
        for (int ks = 0; ks < 8; ks++) {
            const int k0 = ks * 8;
            uint32_t a[2][4];
#pragma unroll
            for (int mi = 0; mi < 2; mi++) {
                const float* ap = &Ps[(rbase + mi * 16) * AST + k0 + (lane & 3)];
                a[mi][0] = __float_as_uint(ap[0]);
                a[mi][1] = __float_as_uint(ap[8 * AST]);
                a[mi][2] = __float_as_uint(ap[4]);
                a[mi][3] = __float_as_uint(ap[8 * AST + 4]);
            }
#pragma unroll
            for (int ni = 0; ni < 8; ni++) {
                const float* bp = &Vb[(k0 + (lane & 3)) * AST + ni * 8 + (lane >> 2)];
                const uint32_t b0 = __float_as_uint(bp[0]);
                const uint32_t b1 = __float_as_uint(bp[4 * AST]);
#pragma unroll
                for (int mi = 0; mi < 2; mi++)
                    mma8(o[mi][ni], a[mi][0], a[mi][1], a[mi][2], a[mi][3],
                         b0, b1);
            }
        }

        if (kt + 2 < NKT) {
            __syncthreads();   // all warps done reading slot s before refill
            attn_stage_kv(Ks_s, Vs_s, s, K, V, kt + 2, tid);
        }
    }

    // epilogue: normalize + round + write (b, s, h*64+dh)
#pragma unroll
    for (int mi = 0; mi < 2; mi++)
#pragma unroll
        for (int hp = 0; hp < 2; hp++) {
            const float inv = 1.f / lrow[mi][hp];
            const int row = qt * 256 + rbase + mi * 16 + hp * 8;
#pragma unroll
            for (int ni = 0; ni < 8; ni++) {
                const int col = h * 64 + ni * 8 + (lane & 3) * 2;
                *reinterpret_cast<float2*>(
                    g_att + (size_t)(b * SS + row) * DD + col) =
                    make_float2(
                        __uint_as_float(f2tf(o[mi][ni][hp * 2] * inv)),
                        __uint_as_float(f2tf(o[mi][ni][hp * 2 + 1] * inv)));
            }
        }
}

// ---------------------------------------------------------------------------
extern "C" void kernel_launch(void* const* d_in, const int* in_sizes, int n_in,
                              void* d_out, int out_size)
{
    const float* x    = (const float*)d_in[0];
    const float* cosT = (const float*)d_in[1];
    const float* sinT = (const float*)d_in[2];
    const float* wq   = (const float*)d_in[3];
    const float* wk   = (const float*)d_in[4];
    const float* wv   = (const float*)d_in[5];
    const float* wo   = (const float*)d_in[6];
    float* out = (float*)d_out;

    static bool attr_set = false;
    if (!attr_set) {
        cudaFuncSetAttribute(qkv_mma,
                             cudaFuncAttributeMaxDynamicSharedMemorySize, GEMM_SMEM);
        cudaFuncSetAttribute(proj_mma,
                             cudaFuncAttributeMaxDynamicSharedMemorySize, GEMM_SMEM);
        cudaFuncSetAttribute(attn_mma,
                             cudaFuncAttributeMaxDynamicSharedMemorySize, ATT_SMEM);
        attr_set = true;
    }

    cvt_inputs<<<dim3(512, 5), 256>>>(x, wq, wk, wv, wo);
    qkv_mma<<<dim3(DD / 128, MT / 128, 3), 128, GEMM_SMEM>>>(cosT, sinT);
    attn_mma<<<dim3(SS / 256, HH, BB), 256, ATT_SMEM>>>();
    proj_mma<<<dim3(DD / 128, MT / 128, 1), 128, GEMM_SMEM>>>(out);
}